// round 3
// baseline (speedup 1.0000x reference)
#include <cuda_runtime.h>

// Problem constants
#define N_TOK 8192   // B*S = 4*2048
#define DIM   1024
#define NEXP  8
#define KSEL  2

// GEMM tiling
#define BM 64     // tokens per block
#define BN 128    // output features per block
#define BK 16     // k-chunk

// ---------------- scratch (no allocations allowed) ----------------
__device__ int   g_cnt[NEXP];
__device__ int   g_tok[NEXP * N_TOK];
__device__ float g_wt [NEXP * N_TOK];
__device__ int   g_texp[N_TOK * 2];
__device__ float g_twt [N_TOK * 2];

// ---------------- kernel 0: zero counters ----------------
__global__ void zero_cnt_kernel() {
    if (threadIdx.x < NEXP) g_cnt[threadIdx.x] = 0;
}

// ---------------- kernel 1: gating ----------------
// One warp per token. gate_W cached in smem padded to stride 9 (gcd(9,32)=1
// -> conflict-free strided reads).
__global__ void gating_kernel(const float* __restrict__ x,
                              const float* __restrict__ gW,
                              const float* __restrict__ gb) {
    __shared__ float sW[DIM * 9];
    int tid = threadIdx.x;
    for (int i = tid; i < DIM * NEXP; i += 256) {
        int d = i >> 3, e = i & 7;
        sW[d * 9 + e] = gW[i];
    }
    __syncthreads();

    int warp = tid >> 5, lane = tid & 31;
    int t = blockIdx.x * 8 + warp;
    const float* xr = x + (size_t)t * DIM;

    float acc[NEXP];
#pragma unroll
    for (int e = 0; e < NEXP; e++) acc[e] = 0.f;

#pragma unroll 8
    for (int i = 0; i < 32; i++) {
        int d = i * 32 + lane;
        float xv = xr[d];
        const float* w = &sW[d * 9];
#pragma unroll
        for (int e = 0; e < NEXP; e++) acc[e] += xv * w[e];
    }

#pragma unroll
    for (int e = 0; e < NEXP; e++) {
#pragma unroll
        for (int off = 16; off > 0; off >>= 1)
            acc[e] += __shfl_down_sync(0xFFFFFFFFu, acc[e], off);
    }

    if (lane == 0) {
        // scores = max(lin + b, EPS); softmax; top-2; weights
        float s[NEXP];
        float m = -1e30f;
#pragma unroll
        for (int e = 0; e < NEXP; e++) {
            s[e] = fmaxf(acc[e] + gb[e], 1e-4f);
            m = fmaxf(m, s[e]);
        }
        float sum = 0.f;
        float p[NEXP];
#pragma unroll
        for (int e = 0; e < NEXP; e++) { p[e] = expf(s[e] - m); sum += p[e]; }
        float inv = 1.f / sum;

        int b1 = 0, b2 = -1;
        float v1 = -1.f, v2 = -1.f;
#pragma unroll
        for (int e = 0; e < NEXP; e++) {
            float pe = p[e] * inv;
            if (pe > v1)      { v2 = v1; b2 = b1; v1 = pe; b1 = e; }
            else if (pe > v2) { v2 = pe; b2 = e; }
        }
        float c1 = fmaxf(v1, 0.1f);
        float c2 = fmaxf(v2, 0.1f);
        float a  = 1.f / ((c1 + c2) * (float)KSEL);
        float a1 = c1 * a, a2 = c2 * a;

        int s1 = atomicAdd(&g_cnt[b1], 1);
        g_tok[b1 * N_TOK + s1] = t;
        g_wt [b1 * N_TOK + s1] = a1;
        int s2 = atomicAdd(&g_cnt[b2], 1);
        g_tok[b2 * N_TOK + s2] = t;
        g_wt [b2 * N_TOK + s2] = a2;

        g_texp[2 * t]     = b1;
        g_texp[2 * t + 1] = b2;
        g_twt [2 * t]     = a1;
        g_twt [2 * t + 1] = a2;
    }
}

// ---------------- kernel 2: init out with combined bias ----------------
__global__ void bias_init_kernel(const float* __restrict__ eb,
                                 float* __restrict__ out) {
    int idx = blockIdx.x * blockDim.x + threadIdx.x;   // < N_TOK*DIM
    int t = idx >> 10, f = idx & 1023;
    int   e1 = g_texp[2 * t],  e2 = g_texp[2 * t + 1];
    float a1 = g_twt[2 * t],   a2 = g_twt[2 * t + 1];
    out[idx] = a1 * eb[e1 * DIM + f] + a2 * eb[e2 * DIM + f];
}

// ---------------- kernel 3: expert-gathered GEMM ----------------
// grid = (DIM/BN, N_TOK/BM, NEXP); blocks beyond an expert's token count exit.
// 256 threads, each computes a 4x8 micro-tile. Epilogue: atomicAdd scaled by
// the per-(token,expert) combine weight.
__global__ __launch_bounds__(256, 3)
void moe_gemm_kernel(const float* __restrict__ x,
                     const float* __restrict__ eW,
                     float* __restrict__ out) {
    __shared__ float Xs[BK][68];    // [k][token], pad -> 272B rows (16B aligned)
    __shared__ float Ws[BK][132];   // [k][f],     pad -> 528B rows (16B aligned)
    __shared__ int   s_tok[BM];
    __shared__ float s_wt [BM];

    int e    = blockIdx.z;
    int cnt  = g_cnt[e];
    int tok0 = blockIdx.y * BM;
    if (tok0 >= cnt) return;
    int f0  = blockIdx.x * BN;
    int tid = threadIdx.x;

    if (tid < BM) {
        int r = tok0 + tid;
        if (r < cnt) {
            s_tok[tid] = g_tok[e * N_TOK + r];
            s_wt [tid] = g_wt [e * N_TOK + r];
        } else {
            s_tok[tid] = 0;
            s_wt [tid] = 0.f;
        }
    }
    __syncthreads();

    // X gather loader: 4 threads per token, float4 along k
    int lm = tid >> 2;           // token 0..63
    int lk = (tid & 3) * 4;      // 0,4,8,12
    const float* xrow = x + (size_t)s_tok[lm] * DIM + lk;

    // W loader: thread covers (wk0, wf0) and (wk0+8, wf0)
    int wk0 = tid >> 5;          // 0..7
    int wf0 = (tid & 31) * 4;    // 0..124
    const float* wbase = eW + (size_t)e * DIM * DIM + f0;

    int ty = tid >> 4, tx = tid & 15;
    int r0 = ty * 4, c0 = tx * 8;

    float acc[4][8];
#pragma unroll
    for (int i = 0; i < 4; i++)
#pragma unroll
        for (int j = 0; j < 8; j++) acc[i][j] = 0.f;

    for (int k0 = 0; k0 < DIM; k0 += BK) {
        float4 xv  = *(const float4*)(xrow + k0);
        float4 wv0 = *(const float4*)(wbase + (size_t)(k0 + wk0)     * DIM + wf0);
        float4 wv1 = *(const float4*)(wbase + (size_t)(k0 + wk0 + 8) * DIM + wf0);
        __syncthreads();
        Xs[lk + 0][lm] = xv.x;
        Xs[lk + 1][lm] = xv.y;
        Xs[lk + 2][lm] = xv.z;
        Xs[lk + 3][lm] = xv.w;
        *(float4*)&Ws[wk0][wf0]     = wv0;
        *(float4*)&Ws[wk0 + 8][wf0] = wv1;
        __syncthreads();

#pragma unroll
        for (int k = 0; k < BK; k++) {
            float4 a  = *(const float4*)&Xs[k][r0];
            float4 b0 = *(const float4*)&Ws[k][c0];
            float4 b1 = *(const float4*)&Ws[k][c0 + 4];
            float av[4] = {a.x, a.y, a.z, a.w};
            float bv[8] = {b0.x, b0.y, b0.z, b0.w, b1.x, b1.y, b1.z, b1.w};
#pragma unroll
            for (int i = 0; i < 4; i++)
#pragma unroll
                for (int j = 0; j < 8; j++)
                    acc[i][j] += av[i] * bv[j];
        }
    }

#pragma unroll
    for (int i = 0; i < 4; i++) {
        int r = r0 + i;
        if (tok0 + r < cnt) {
            int   t = s_tok[r];
            float w = s_wt [r];
            float* op = out + (size_t)t * DIM + f0 + c0;
#pragma unroll
            for (int j = 0; j < 8; j++)
                atomicAdd(&op[j], acc[i][j] * w);
        }
    }
}

// ---------------- launch ----------------
extern "C" void kernel_launch(void* const* d_in, const int* in_sizes, int n_in,
                              void* d_out, int out_size) {
    const float* x  = (const float*)d_in[0];  // [4,2048,1024]
    const float* gW = (const float*)d_in[1];  // [1024,8]
    const float* gb = (const float*)d_in[2];  // [8]
    const float* eW = (const float*)d_in[3];  // [8,1024,1024]
    const float* eb = (const float*)d_in[4];  // [8,1024]
    float* out = (float*)d_out;               // [4,2048,1024]
    (void)in_sizes; (void)n_in; (void)out_size;

    zero_cnt_kernel<<<1, 32>>>();
    gating_kernel<<<N_TOK / 8, 256>>>(x, gW, gb);
    bias_init_kernel<<<(N_TOK * DIM) / 256, 256>>>(eb, out);

    dim3 grid(DIM / BN, N_TOK / BM, NEXP);
    moe_gemm_kernel<<<grid, 256>>>(x, eW, out);
}

// round 8
// speedup vs baseline: 3.3106x; 3.3106x over previous
#include <cuda_runtime.h>
#include <cstdint>

// ---------------- problem constants ----------------
#define N_TOK 8192
#define DIM   1024
#define NEXP  8

// ---------------- GEMM tiling ----------------
#define BM 128
#define BN 128
#define BK 32
#define NK (DIM / BK)        // 32 k-stages
#define NSTAGE 3

#define A_STRIDE 36          // floats per A smem row (pad: conflict-free)
#define B_STRIDE 136         // floats per B smem row (pad: conflict-free)
#define ASZ (BM * A_STRIDE * 4)   // 18432 B per stage
#define BSZ (BK * B_STRIDE * 4)   // 17408 B per stage

#define SM_TOK 0
#define SM_A   512
#define SM_B   (SM_A + NSTAGE * ASZ)
#define SMEM_ALLOC (SM_B + NSTAGE * BSZ)   // 108032 B

// ---------------- scratch ----------------
__device__ int   g_cnt[NEXP];
__device__ int   g_off[NEXP];
__device__ int   g_tok[NEXP * N_TOK];
__device__ int   g_texp[N_TOK * 2];
__device__ int   g_slot[N_TOK * 2];
__device__ float g_twt [N_TOK * 2];
__device__ float g_xr[N_TOK * DIM];        // x rounded to tf32
__device__ float g_wr[NEXP * DIM * DIM];   // W rounded to tf32
__device__ float g_y [2 * N_TOK * DIM];    // per (expert,slot) GEMM result

// ---------------- helpers ----------------
__device__ __forceinline__ uint32_t smem_u32(const void* p) {
    uint32_t a;
    asm("{ .reg .u64 t; cvta.to.shared.u64 t, %1; cvt.u32.u64 %0, t; }"
        : "=r"(a) : "l"(p));
    return a;
}
__device__ __forceinline__ float tf32r(float v) {
    uint32_t u;
    asm("cvt.rna.tf32.f32 %0, %1;" : "=r"(u) : "f"(v));
    return __uint_as_float(u);
}
__device__ __forceinline__ void cp16(uint32_t dst, const void* src) {
    asm volatile("cp.async.cg.shared.global [%0], [%1], 16;" :: "r"(dst), "l"(src));
}
#define CP_COMMIT() asm volatile("cp.async.commit_group;" ::: "memory")
#define CP_WAIT(n)  asm volatile("cp.async.wait_group %0;" :: "n"(n) : "memory")

__device__ __forceinline__ void mma_tf32(float* c, const uint32_t* a,
                                         uint32_t b0, uint32_t b1) {
    asm volatile(
        "mma.sync.aligned.m16n8k8.row.col.f32.tf32.tf32.f32 "
        "{%0,%1,%2,%3}, {%4,%5,%6,%7}, {%8,%9}, {%0,%1,%2,%3};"
        : "+f"(c[0]), "+f"(c[1]), "+f"(c[2]), "+f"(c[3])
        : "r"(a[0]), "r"(a[1]), "r"(a[2]), "r"(a[3]), "r"(b0), "r"(b1));
}

// ---------------- kernel: zero counters ----------------
__global__ void zero_cnt_kernel() {
    if (threadIdx.x < NEXP) g_cnt[threadIdx.x] = 0;
}

// ---------------- kernel: gating (warp per token) ----------------
__global__ void gating_kernel(const float* __restrict__ x,
                              const float* __restrict__ gW,
                              const float* __restrict__ gb) {
    __shared__ float sW[DIM * 9];
    int tid = threadIdx.x;
    for (int i = tid; i < DIM * NEXP; i += 256) {
        int d = i >> 3, e = i & 7;
        sW[d * 9 + e] = gW[i];
    }
    __syncthreads();

    int warp = tid >> 5, lane = tid & 31;
    int t = blockIdx.x * 8 + warp;
    const float* xr = x + (size_t)t * DIM;

    float acc[NEXP];
#pragma unroll
    for (int e = 0; e < NEXP; e++) acc[e] = 0.f;
#pragma unroll 8
    for (int i = 0; i < 32; i++) {
        int d = i * 32 + lane;
        float xv = xr[d];
        const float* w = &sW[d * 9];
#pragma unroll
        for (int e = 0; e < NEXP; e++) acc[e] += xv * w[e];
    }
#pragma unroll
    for (int e = 0; e < NEXP; e++) {
#pragma unroll
        for (int off = 16; off > 0; off >>= 1)
            acc[e] += __shfl_down_sync(0xFFFFFFFFu, acc[e], off);
    }

    if (lane == 0) {
        float s[NEXP], p[NEXP];
        float m = -1e30f;
#pragma unroll
        for (int e = 0; e < NEXP; e++) {
            s[e] = fmaxf(acc[e] + gb[e], 1e-4f);
            m = fmaxf(m, s[e]);
        }
        float sum = 0.f;
#pragma unroll
        for (int e = 0; e < NEXP; e++) { p[e] = expf(s[e] - m); sum += p[e]; }
        float inv = 1.f / sum;

        int b1 = 0, b2 = -1;
        float v1 = -1.f, v2 = -1.f;
#pragma unroll
        for (int e = 0; e < NEXP; e++) {
            float pe = p[e] * inv;
            if (pe > v1)      { v2 = v1; b2 = b1; v1 = pe; b1 = e; }
            else if (pe > v2) { v2 = pe; b2 = e; }
        }
        float c1 = fmaxf(v1, 0.1f);
        float c2 = fmaxf(v2, 0.1f);
        float a  = 1.f / ((c1 + c2) * 2.0f);
        float a1 = c1 * a, a2 = c2 * a;

        int s1 = atomicAdd(&g_cnt[b1], 1);
        g_tok[b1 * N_TOK + s1] = t;
        int s2 = atomicAdd(&g_cnt[b2], 1);
        g_tok[b2 * N_TOK + s2] = t;

        g_texp[2 * t] = b1;  g_texp[2 * t + 1] = b2;
        g_slot[2 * t] = s1;  g_slot[2 * t + 1] = s2;
        g_twt [2 * t] = a1;  g_twt [2 * t + 1] = a2;
    }
}

// ---------------- kernel: prefix offsets ----------------
__global__ void scan_kernel() {
    if (threadIdx.x == 0) {
        int o = 0;
        for (int e = 0; e < NEXP; e++) { g_off[e] = o; o += g_cnt[e]; }
    }
}

// ---------------- kernels: round to tf32 (RN) ----------------
__global__ void round_x_kernel(const float* __restrict__ x) {
    int i = blockIdx.x * 256 + threadIdx.x;
    float4 v = ((const float4*)x)[i];
    v.x = tf32r(v.x); v.y = tf32r(v.y); v.z = tf32r(v.z); v.w = tf32r(v.w);
    ((float4*)g_xr)[i] = v;
}
__global__ void round_w_kernel(const float* __restrict__ eW) {
    int i = blockIdx.x * 256 + threadIdx.x;
    float4 v = ((const float4*)eW)[i];
    v.x = tf32r(v.x); v.y = tf32r(v.y); v.z = tf32r(v.z); v.w = tf32r(v.w);
    ((float4*)g_wr)[i] = v;
}

// ---------------- GEMM stage loader ----------------
__device__ __forceinline__ void load_stage(uint32_t sb, const int* s_tok,
                                           int e, int f0, int slot, int s) {
    int tid = threadIdx.x;
    int k0 = s * BK;
    // A: 128 rows x 32 floats, 2 threads per row, 4 cp16 each
    {
        int r = tid >> 1, cb = (tid & 1) * 4;
        const float* src = g_xr + (size_t)s_tok[r] * DIM + k0;
        uint32_t dst = sb + SM_A + slot * ASZ + r * (A_STRIDE * 4);
#pragma unroll
        for (int i = 0; i < 4; i++)
            cp16(dst + (cb + i) * 16, src + (cb + i) * 4);
    }
    // B: 32 rows (k) x 128 floats (n), 8 threads per row, 4 cp16 each
    {
        int kr = tid >> 3, c4 = tid & 7;
        const float* src = g_wr + ((size_t)e << 20) + (size_t)(k0 + kr) * DIM + f0;
        uint32_t dst = sb + SM_B + slot * BSZ + kr * (B_STRIDE * 4);
#pragma unroll
        for (int i = 0; i < 4; i++)
            cp16(dst + (c4 + 8 * i) * 16, src + (c4 + 8 * i) * 4);
    }
    CP_COMMIT();
}

// ---------------- kernel: tf32 mma.sync gathered GEMM ----------------
__global__ __launch_bounds__(256, 1)
void moe_gemm_mma() {
    extern __shared__ char smem[];
    int e     = blockIdx.z;
    int cnt   = g_cnt[e];
    int tile0 = blockIdx.y * BM;
    if (tile0 >= cnt) return;
    int f0  = blockIdx.x * BN;
    int tid = threadIdx.x;
    int wid = tid >> 5, lane = tid & 31;
    int g = lane >> 2, t = lane & 3;
    int wm = wid & 1, wn = wid >> 1;       // warp tile: rows wm*64, cols wn*32

    uint32_t sb = smem_u32(smem);
    int* s_tok = (int*)(smem + SM_TOK);
    for (int i = tid; i < BM; i += 256) {
        int r = tile0 + i;
        s_tok[i] = g_tok[e * N_TOK + (r < cnt ? r : 0)];
    }
    __syncthreads();

    float acc[4][4][4];
#pragma unroll
    for (int i = 0; i < 4; i++)
#pragma unroll
        for (int j = 0; j < 4; j++)
#pragma unroll
            for (int q = 0; q < 4; q++) acc[i][j][q] = 0.f;

#pragma unroll
    for (int p = 0; p < NSTAGE - 1; p++)
        load_stage(sb, s_tok, e, f0, p, p);

    for (int s = 0; s < NK; s++) {
        if (s + NSTAGE - 1 < NK) {
            load_stage(sb, s_tok, e, f0, (s + NSTAGE - 1) % NSTAGE, s + NSTAGE - 1);
            CP_WAIT(NSTAGE - 1);
        } else {
            CP_WAIT(0);
        }
        __syncthreads();

        const float* As = (const float*)(smem + SM_A + (s % NSTAGE) * ASZ);
        const float* Bs = (const float*)(smem + SM_B + (s % NSTAGE) * BSZ);
#pragma unroll
        for (int ks = 0; ks < 4; ks++) {
            int k0 = ks * 8;
            uint32_t a[4][4];
#pragma unroll
            for (int i = 0; i < 4; i++) {
                const float* ap = As + (wm * 64 + i * 16 + g) * A_STRIDE + k0 + t;
                a[i][0] = __float_as_uint(ap[0]);
                a[i][1] = __float_as_uint(ap[8 * A_STRIDE]);
                a[i][2] = __float_as_uint(ap[4]);
                a[i][3] = __float_as_uint(ap[8 * A_STRIDE + 4]);
            }
#pragma unroll
            for (int j = 0; j < 4; j++) {
                const float* bp = Bs + (k0 + t) * B_STRIDE + wn * 32 + j * 8 + g;
                uint32_t b0 = __float_as_uint(bp[0]);
                uint32_t b1 = __float_as_uint(bp[4 * B_STRIDE]);
#pragma unroll
                for (int i = 0; i < 4; i++)
                    mma_tf32(acc[i][j], a[i], b0, b1);
            }
        }
        __syncthreads();
    }

    // epilogue: write to staging y
    int rowbase = g_off[e] + tile0;
#pragma unroll
    for (int i = 0; i < 4; i++) {
        int r0 = wm * 64 + i * 16 + g;
#pragma unroll
        for (int j = 0; j < 4; j++) {
            int col = f0 + wn * 32 + j * 8 + t * 2;
            if (tile0 + r0 < cnt) {
                float2 v = make_float2(acc[i][j][0], acc[i][j][1]);
                *(float2*)(g_y + (size_t)(rowbase + r0) * DIM + col) = v;
            }
            if (tile0 + r0 + 8 < cnt) {
                float2 v = make_float2(acc[i][j][2], acc[i][j][3]);
                *(float2*)(g_y + (size_t)(rowbase + r0 + 8) * DIM + col) = v;
            }
        }
    }
}

// ---------------- kernel: combine ----------------
__global__ void combine_kernel(const float* __restrict__ eb,
                               float* __restrict__ out) {
    int tid = blockIdx.x * 256 + threadIdx.x;
    int t = tid >> 6, j = tid & 63;
    int e1 = g_texp[2 * t], e2 = g_texp[2 * t + 1];
    float a1 = g_twt[2 * t], a2 = g_twt[2 * t + 1];
    int r1 = g_off[e1] + g_slot[2 * t];
    int r2 = g_off[e2] + g_slot[2 * t + 1];
    const float4* y1 = (const float4*)(g_y + (size_t)r1 * DIM);
    const float4* y2 = (const float4*)(g_y + (size_t)r2 * DIM);
    const float4* b1 = (const float4*)(eb + (size_t)e1 * DIM);
    const float4* b2 = (const float4*)(eb + (size_t)e2 * DIM);
    float4* o = (float4*)(out + (size_t)t * DIM);
#pragma unroll
    for (int q = 0; q < 4; q++) {
        int f = j + 64 * q;
        float4 v1 = y1[f], v2 = y2[f], c1 = b1[f], c2 = b2[f];
        float4 r;
        r.x = a1 * (v1.x + c1.x) + a2 * (v2.x + c2.x);
        r.y = a1 * (v1.y + c1.y) + a2 * (v2.y + c2.y);
        r.z = a1 * (v1.z + c1.z) + a2 * (v2.z + c2.z);
        r.w = a1 * (v1.w + c1.w) + a2 * (v2.w + c2.w);
        o[f] = r;
    }
}

// ---------------- launch ----------------
extern "C" void kernel_launch(void* const* d_in, const int* in_sizes, int n_in,
                              void* d_out, int out_size) {
    const float* x  = (const float*)d_in[0];
    const float* gW = (const float*)d_in[1];
    const float* gb = (const float*)d_in[2];
    const float* eW = (const float*)d_in[3];
    const float* eb = (const float*)d_in[4];
    float* out = (float*)d_out;
    (void)in_sizes; (void)n_in; (void)out_size;

    zero_cnt_kernel<<<1, 32>>>();
    gating_kernel<<<N_TOK / 8, 256>>>(x, gW, gb);
    scan_kernel<<<1, 1>>>();
    round_x_kernel<<<(N_TOK * DIM / 4) / 256, 256>>>(x);
    round_w_kernel<<<(NEXP * DIM * DIM / 4) / 256, 256>>>(eW);

    cudaFuncSetAttribute(moe_gemm_mma,
                         cudaFuncAttributeMaxDynamicSharedMemorySize, SMEM_ALLOC);
    moe_gemm_mma<<<dim3(DIM / BN, N_TOK / BM, NEXP), 256, SMEM_ALLOC>>>();

    combine_kernel<<<(N_TOK * 64) / 256, 256>>>(eb, out);
}

// round 9
// speedup vs baseline: 3.7360x; 1.1285x over previous
#include <cuda_runtime.h>
#include <cstdint>

// ---------------- problem constants ----------------
#define N_TOK 8192
#define DIM   1024
#define NEXP  8

// ---------------- GEMM tiling ----------------
#define BM 128               // rows per CTA
#define BN 256               // cols per CTA
#define BK 16                // k per stage
#define NK (DIM / BK)        // 64 k-stages
#define NSTAGE 4

#define A_STRIDE 20          // floats per A smem row (conflict-free pad)
#define B_STRIDE 264         // floats per B smem row (conflict-free pad)
#define ASZ (BM * A_STRIDE * 4)   // 10240 B per stage
#define BSZ (BK * B_STRIDE * 4)   // 16896 B per stage

#define SM_TOK 0
#define SM_A   512
#define SM_B   (SM_A + NSTAGE * ASZ)          // 41472
#define SMEM_ALLOC (SM_B + NSTAGE * BSZ)      // 109056 B

// ---------------- scratch ----------------
__device__ int   g_cnt[NEXP];
__device__ int   g_off[NEXP];
__device__ int   g_tok[NEXP * N_TOK];
__device__ int   g_texp[N_TOK * 2];
__device__ int   g_slot[N_TOK * 2];
__device__ float g_twt [N_TOK * 2];
__device__ float g_xr[N_TOK * DIM];        // x rounded to tf32
__device__ float g_wr[NEXP * DIM * DIM];   // W rounded to tf32
__device__ float g_y [2 * N_TOK * DIM];    // per (expert,slot) GEMM result

// ---------------- helpers ----------------
__device__ __forceinline__ uint32_t smem_u32(const void* p) {
    uint32_t a;
    asm("{ .reg .u64 t; cvta.to.shared.u64 t, %1; cvt.u32.u64 %0, t; }"
        : "=r"(a) : "l"(p));
    return a;
}
__device__ __forceinline__ float tf32r(float v) {
    uint32_t u;
    asm("cvt.rna.tf32.f32 %0, %1;" : "=r"(u) : "f"(v));
    return __uint_as_float(u);
}
__device__ __forceinline__ void cp16(uint32_t dst, const void* src) {
    asm volatile("cp.async.cg.shared.global [%0], [%1], 16;" :: "r"(dst), "l"(src));
}
#define CP_COMMIT() asm volatile("cp.async.commit_group;" ::: "memory")
#define CP_WAIT(n)  asm volatile("cp.async.wait_group %0;" :: "n"(n) : "memory")

__device__ __forceinline__ void mma_tf32(float* c, const uint32_t* a,
                                         uint32_t b0, uint32_t b1) {
    asm volatile(
        "mma.sync.aligned.m16n8k8.row.col.f32.tf32.tf32.f32 "
        "{%0,%1,%2,%3}, {%4,%5,%6,%7}, {%8,%9}, {%0,%1,%2,%3};"
        : "+f"(c[0]), "+f"(c[1]), "+f"(c[2]), "+f"(c[3])
        : "r"(a[0]), "r"(a[1]), "r"(a[2]), "r"(a[3]), "r"(b0), "r"(b1));
}

// ---------------- kernel: zero counters ----------------
__global__ void zero_cnt_kernel() {
    if (threadIdx.x < NEXP) g_cnt[threadIdx.x] = 0;
}

// ---------------- kernel: gating + x tf32 round (fused) ----------------
__global__ void gating_kernel(const float* __restrict__ x,
                              const float* __restrict__ gW,
                              const float* __restrict__ gb) {
    __shared__ float sW[DIM * 9];
    int tid = threadIdx.x;
    for (int i = tid; i < DIM * NEXP; i += 256) {
        int d = i >> 3, e = i & 7;
        sW[d * 9 + e] = gW[i];
    }
    __syncthreads();

    int warp = tid >> 5, lane = tid & 31;
    int t = blockIdx.x * 8 + warp;
    const float* xrow = x + (size_t)t * DIM;
    float*       xout = g_xr + (size_t)t * DIM;

    float acc[NEXP];
#pragma unroll
    for (int e = 0; e < NEXP; e++) acc[e] = 0.f;
#pragma unroll 8
    for (int i = 0; i < 32; i++) {
        int d = i * 32 + lane;
        float xv = xrow[d];
        xout[d] = tf32r(xv);                 // fused tf32 round of x
        const float* w = &sW[d * 9];
#pragma unroll
        for (int e = 0; e < NEXP; e++) acc[e] += xv * w[e];
    }
#pragma unroll
    for (int e = 0; e < NEXP; e++) {
#pragma unroll
        for (int off = 16; off > 0; off >>= 1)
            acc[e] += __shfl_down_sync(0xFFFFFFFFu, acc[e], off);
    }

    if (lane == 0) {
        float s[NEXP], p[NEXP];
        float m = -1e30f;
#pragma unroll
        for (int e = 0; e < NEXP; e++) {
            s[e] = fmaxf(acc[e] + gb[e], 1e-4f);
            m = fmaxf(m, s[e]);
        }
        float sum = 0.f;
#pragma unroll
        for (int e = 0; e < NEXP; e++) { p[e] = expf(s[e] - m); sum += p[e]; }
        float inv = 1.f / sum;

        int b1 = 0, b2 = -1;
        float v1 = -1.f, v2 = -1.f;
#pragma unroll
        for (int e = 0; e < NEXP; e++) {
            float pe = p[e] * inv;
            if (pe > v1)      { v2 = v1; b2 = b1; v1 = pe; b1 = e; }
            else if (pe > v2) { v2 = pe; b2 = e; }
        }
        float c1 = fmaxf(v1, 0.1f);
        float c2 = fmaxf(v2, 0.1f);
        float a  = 1.f / ((c1 + c2) * 2.0f);
        float a1 = c1 * a, a2 = c2 * a;

        int s1 = atomicAdd(&g_cnt[b1], 1);
        g_tok[b1 * N_TOK + s1] = t;
        int s2 = atomicAdd(&g_cnt[b2], 1);
        g_tok[b2 * N_TOK + s2] = t;

        g_texp[2 * t] = b1;  g_texp[2 * t + 1] = b2;
        g_slot[2 * t] = s1;  g_slot[2 * t + 1] = s2;
        g_twt [2 * t] = a1;  g_twt [2 * t + 1] = a2;
    }
}

// ---------------- kernel: prefix offsets ----------------
__global__ void scan_kernel() {
    if (threadIdx.x == 0) {
        int o = 0;
        for (int e = 0; e < NEXP; e++) { g_off[e] = o; o += g_cnt[e]; }
    }
}

// ---------------- kernel: round W to tf32 (RN), 4x float4 per thread ----------------
__global__ void round_w_kernel(const float* __restrict__ eW) {
    int base = (blockIdx.x * 256 + threadIdx.x) * 4;
    float4 v[4];
#pragma unroll
    for (int q = 0; q < 4; q++) v[q] = ((const float4*)eW)[base + q];
#pragma unroll
    for (int q = 0; q < 4; q++) {
        v[q].x = tf32r(v[q].x); v[q].y = tf32r(v[q].y);
        v[q].z = tf32r(v[q].z); v[q].w = tf32r(v[q].w);
        ((float4*)g_wr)[base + q] = v[q];
    }
}

// ---------------- kernel: tf32 mma.sync gathered GEMM ----------------
__global__ __launch_bounds__(256, 1)
void moe_gemm_mma() {
    extern __shared__ char smem[];
    int e     = blockIdx.z;
    int cnt   = g_cnt[e];
    int tile0 = blockIdx.y * BM;
    if (tile0 >= cnt) return;
    int f0  = blockIdx.x * BN;
    int tid = threadIdx.x;
    int wid = tid >> 5, lane = tid & 31;
    int g = lane >> 2, t = lane & 3;
    int wm = wid & 1, wn = wid >> 1;        // warp tile: 64 rows x 64 cols

    uint32_t sb = smem_u32(smem);
    int* s_tok = (int*)(smem + SM_TOK);
    for (int i = tid; i < BM; i += 256) {
        int r = tile0 + i;
        s_tok[i] = g_tok[e * N_TOK + (r < cnt ? r : 0)];
    }
    __syncthreads();

    // loader base pointers (fixed per thread)
    int ar = tid >> 1, ah = tid & 1;
    const float* aSrc = g_xr + (size_t)s_tok[ar] * DIM + ah * 8;
    uint32_t     aDst = sb + SM_A + ar * (A_STRIDE * 4) + ah * 32;
    int bkr = tid >> 4, bcc = tid & 15;
    const float* bSrc = g_wr + ((size_t)e << 20) + (size_t)bkr * DIM + f0 + bcc * 4;
    uint32_t     bDst = sb + SM_B + bkr * (B_STRIDE * 4) + bcc * 16;

#define LOAD_STAGE(slot, s)                                              \
    do {                                                                 \
        int k0_ = (s) * BK;                                              \
        const float* sa_ = aSrc + k0_;                                   \
        uint32_t da_ = aDst + (slot) * ASZ;                              \
        cp16(da_, sa_); cp16(da_ + 16, sa_ + 4);                         \
        const float* sb_ = bSrc + (size_t)k0_ * DIM;                     \
        uint32_t db_ = bDst + (slot) * BSZ;                              \
        cp16(db_,       sb_);                                            \
        cp16(db_ + 256, sb_ + 64);                                       \
        cp16(db_ + 512, sb_ + 128);                                      \
        cp16(db_ + 768, sb_ + 192);                                      \
        CP_COMMIT();                                                     \
    } while (0)

    float acc[4][8][4];
#pragma unroll
    for (int i = 0; i < 4; i++)
#pragma unroll
        for (int j = 0; j < 8; j++)
#pragma unroll
            for (int q = 0; q < 4; q++) acc[i][j][q] = 0.f;

#pragma unroll
    for (int p = 0; p < NSTAGE - 1; p++) LOAD_STAGE(p, p);

    for (int s = 0; s < NK; s++) {
        CP_WAIT(NSTAGE - 2);
        __syncthreads();     // one barrier per iter: protects slot (s-1)%NSTAGE
        if (s + NSTAGE - 1 < NK) {
            LOAD_STAGE((s + NSTAGE - 1) % NSTAGE, s + NSTAGE - 1);
        } else {
            CP_COMMIT();     // keep group arithmetic consistent in the tail
        }

        int slot = s % NSTAGE;
        const float* As = (const float*)(smem + SM_A + slot * ASZ);
        const float* Bs = (const float*)(smem + SM_B + slot * BSZ);
#pragma unroll
        for (int ks = 0; ks < 2; ks++) {
            int k0 = ks * 8;
            uint32_t a[4][4];
#pragma unroll
            for (int i = 0; i < 4; i++) {
                const float* ap = As + (wm * 64 + i * 16 + g) * A_STRIDE + k0 + t;
                a[i][0] = __float_as_uint(ap[0]);
                a[i][1] = __float_as_uint(ap[8 * A_STRIDE]);
                a[i][2] = __float_as_uint(ap[4]);
                a[i][3] = __float_as_uint(ap[8 * A_STRIDE + 4]);
            }
            uint32_t bb[8][2];
#pragma unroll
            for (int j = 0; j < 8; j++) {
                const float* bp = Bs + (k0 + t) * B_STRIDE + wn * 64 + j * 8 + g;
                bb[j][0] = __float_as_uint(bp[0]);
                bb[j][1] = __float_as_uint(bp[4 * B_STRIDE]);
            }
#pragma unroll
            for (int j = 0; j < 8; j++)
#pragma unroll
                for (int i = 0; i < 4; i++)
                    mma_tf32(acc[i][j], a[i], bb[j][0], bb[j][1]);
        }
    }

    // epilogue: write to staging y
    int rowbase = g_off[e] + tile0;
#pragma unroll
    for (int i = 0; i < 4; i++) {
        int r0 = wm * 64 + i * 16 + g;
#pragma unroll
        for (int j = 0; j < 8; j++) {
            int col = f0 + wn * 64 + j * 8 + t * 2;
            if (tile0 + r0 < cnt) {
                float2 v = make_float2(acc[i][j][0], acc[i][j][1]);
                *(float2*)(g_y + (size_t)(rowbase + r0) * DIM + col) = v;
            }
            if (tile0 + r0 + 8 < cnt) {
                float2 v = make_float2(acc[i][j][2], acc[i][j][3]);
                *(float2*)(g_y + (size_t)(rowbase + r0 + 8) * DIM + col) = v;
            }
        }
    }
#undef LOAD_STAGE
}

// ---------------- kernel: combine ----------------
__global__ void combine_kernel(const float* __restrict__ eb,
                               float* __restrict__ out) {
    int tid = blockIdx.x * 256 + threadIdx.x;
    int t = tid >> 6, j = tid & 63;
    int e1 = g_texp[2 * t], e2 = g_texp[2 * t + 1];
    float a1 = g_twt[2 * t], a2 = g_twt[2 * t + 1];
    int r1 = g_off[e1] + g_slot[2 * t];
    int r2 = g_off[e2] + g_slot[2 * t + 1];
    const float4* y1 = (const float4*)(g_y + (size_t)r1 * DIM);
    const float4* y2 = (const float4*)(g_y + (size_t)r2 * DIM);
    const float4* b1 = (const float4*)(eb + (size_t)e1 * DIM);
    const float4* b2 = (const float4*)(eb + (size_t)e2 * DIM);
    float4* o = (float4*)(out + (size_t)t * DIM);
#pragma unroll
    for (int q = 0; q < 4; q++) {
        int f = j + 64 * q;
        float4 v1 = y1[f], v2 = y2[f], c1 = b1[f], c2 = b2[f];
        float4 r;
        r.x = a1 * (v1.x + c1.x) + a2 * (v2.x + c2.x);
        r.y = a1 * (v1.y + c1.y) + a2 * (v2.y + c2.y);
        r.z = a1 * (v1.z + c1.z) + a2 * (v2.z + c2.z);
        r.w = a1 * (v1.w + c1.w) + a2 * (v2.w + c2.w);
        o[f] = r;
    }
}

// ---------------- launch ----------------
extern "C" void kernel_launch(void* const* d_in, const int* in_sizes, int n_in,
                              void* d_out, int out_size) {
    const float* x  = (const float*)d_in[0];
    const float* gW = (const float*)d_in[1];
    const float* gb = (const float*)d_in[2];
    const float* eW = (const float*)d_in[3];
    const float* eb = (const float*)d_in[4];
    float* out = (float*)d_out;
    (void)in_sizes; (void)n_in; (void)out_size;

    zero_cnt_kernel<<<1, 32>>>();
    gating_kernel<<<N_TOK / 8, 256>>>(x, gW, gb);
    scan_kernel<<<1, 1>>>();
    round_w_kernel<<<(NEXP * DIM * DIM / 16) / 256, 256>>>(eW);

    cudaFuncSetAttribute(moe_gemm_mma,
                         cudaFuncAttributeMaxDynamicSharedMemorySize, SMEM_ALLOC);
    moe_gemm_mma<<<dim3(DIM / BN, N_TOK / BM, NEXP), 256, SMEM_ALLOC>>>();

    combine_kernel<<<(N_TOK * 64) / 256, 256>>>(eb, out);
}